// round 13
// baseline (speedup 1.0000x reference)
#include <cuda_runtime.h>

// RNNModel: 2-layer tanh RNN + FC, B=2048, T=512, I=8, H=64.
// R12: R11 diet kernel squeezed to 128 regs for 4 blocks/SM (16 warps).
//  - __launch_bounds__(128, 4): reg cap 128 (R9 proved 96 weight regs fit).
//  - All four h buffers in ONE contiguous shared array -> every LDS/STS is
//    one khoff/jidx register + compile-time immediate (fewer address regs).
//  - Otherwise identical to R11: weights pre-scaled by 2*log2(e), bias folded
//    into ks==0 accumulator init, x-term split across k-halves, lag-1 layer
//    pipeline, 1 bar/step, parity unroll x2, skewed broadcast LDS.

#define TT 512
#define HH 64
#define NTHREADS 128
#define BB 2048
#define FULLMASK 0xffffffffu
#define HROW 72          // 64 + skew pad; half0 at [0,32), half1 at [36,68)
#define LOG2E2 2.8853900817779268f   // 2*log2(e)

typedef unsigned long long ull;

__device__ __forceinline__ ull ffma2(ull a, ull b, ull c) {
    ull d; asm("fma.rn.f32x2 %0, %1, %2, %3;" : "=l"(d) : "l"(a), "l"(b), "l"(c)); return d;
}
__device__ __forceinline__ ull fadd2(ull a, ull b) {
    ull d; asm("add.rn.f32x2 %0, %1, %2;" : "=l"(d) : "l"(a), "l"(b)); return d;
}
__device__ __forceinline__ ull fmul2(ull a, ull b) {
    ull d; asm("mul.rn.f32x2 %0, %1, %2;" : "=l"(d) : "l"(a), "l"(b)); return d;
}
__device__ __forceinline__ ull pack2(float lo, float hi) {
    ull d; asm("mov.b64 %0, {%1, %2};" : "=l"(d) : "f"(lo), "f"(hi)); return d;
}
__device__ __forceinline__ float hsum1(ull a) {
    float2 f; asm("mov.b64 {%0, %1}, %2;" : "=f"(f.x), "=f"(f.y) : "l"(a));
    return f.x + f.y;
}
__device__ __forceinline__ float hsum2(ull a, ull b) { return hsum1(fadd2(a, b)); }
__device__ __forceinline__ float hsum4(ull a0, ull a1, ull a2, ull a3) {
    return hsum1(fadd2(fadd2(a0, a1), fadd2(a2, a3)));
}
// Argument is PRE-SCALED by 2*log2(e): tanh(z) = 1 - 2/(exp2(z*2log2e)+1).
__device__ __forceinline__ float fast_tanh_scaled(float zs) {
    float e; asm("ex2.approx.f32 %0, %1;" : "=f"(e) : "f"(zs));
    float r; asm("rcp.approx.f32 %0, %1;" : "=f"(r) : "f"(e + 1.f));
    return fmaf(-2.f, r, 1.f);
}

__global__ void __launch_bounds__(NTHREADS, 4)
rnn_diet4_kernel(const float* __restrict__ x,
                 const float* __restrict__ W_ih0,
                 const float* __restrict__ W_hh0,
                 const float* __restrict__ b_ih0,
                 const float* __restrict__ b_hh0,
                 const float* __restrict__ W_ih1,
                 const float* __restrict__ W_hh1,
                 const float* __restrict__ b_ih1,
                 const float* __restrict__ b_hh1,
                 const float* __restrict__ fc_w,
                 const float* __restrict__ fc_b,
                 float* __restrict__ out)
{
    // One contiguous block: [0]=h0 parity0, [1]=h0 parity1,
    //                       [2]=h1 parity0, [3]=h1 parity1.
    __shared__ __align__(16) float sbuf[4][HROW];
    __shared__ float sfc[4];

    const int tid  = threadIdx.x;
    const int warp = tid >> 5;
    const int lane = tid & 31;
    const int jl   = lane & 15;
    const int ks   = lane >> 4;              // k half
    const int j    = warp * 16 + jl;
    const int jidx = j + ((j >> 5) << 2);    // skewed store index
    const int khoff = ks * 36;               // skewed read offset (floats)
    const int e    = blockIdx.x;

    if (tid < HROW) { sbuf[2][tid] = 0.f; sbuf[3][tid] = 0.f; }

    const ull CC = pack2(LOG2E2, LOG2E2);

    // ---- Per-lane half-k weight rows, PRE-SCALED by 2log2e ----
    ull whh0h[16], wih1h[16], whh1h[16], wih0s[2];
    {
        const ulonglong2* p = (const ulonglong2*)(W_hh0 + j * HH + ks * 32);
        #pragma unroll
        for (int i = 0; i < 8; i++) {
            ulonglong2 v = p[i];
            whh0h[2*i] = fmul2(v.x, CC); whh0h[2*i+1] = fmul2(v.y, CC);
        }
    }
    {
        const ulonglong2* p = (const ulonglong2*)(W_ih1 + j * HH + ks * 32);
        #pragma unroll
        for (int i = 0; i < 8; i++) {
            ulonglong2 v = p[i];
            wih1h[2*i] = fmul2(v.x, CC); wih1h[2*i+1] = fmul2(v.y, CC);
        }
    }
    {
        const ulonglong2* p = (const ulonglong2*)(W_hh1 + j * HH + ks * 32);
        #pragma unroll
        for (int i = 0; i < 8; i++) {
            ulonglong2 v = p[i];
            whh1h[2*i] = fmul2(v.x, CC); whh1h[2*i+1] = fmul2(v.y, CC);
        }
    }
    {   // W_ih0 row j, this lane's k-quarter of I=8: cols [ks*4, ks*4+4)
        const ulonglong2* p = (const ulonglong2*)(W_ih0 + j * 8 + ks * 4);
        ulonglong2 v = p[0];
        wih0s[0] = fmul2(v.x, CC); wih0s[1] = fmul2(v.y, CC);
    }

    // Biases pre-scaled, packed as (b, 0) -- ONLY on the ks==0 half so the
    // cross-half shfl reduce counts each bias exactly once.
    ull pb0 = pack2((b_ih0[j] + b_hh0[j]) * LOG2E2, 0.f);
    ull pb1 = pack2((b_ih1[j] + b_hh1[j]) * LOG2E2, 0.f);
    if (ks == 1) { pb0 = 0ull; pb1 = 0ull; }

    float fcw = fc_w[j];
    if (ks == 1) fcw = 0.f;                  // count each j once in FC reduce

    __syncthreads();

    // x: lane reads its k-quarter (float4) of step t: index t*2 + ks (ulonglong2).
    const ulonglong2* xp = (const ulonglong2*)(x + (size_t)e * TT * 8) + ks;
    ulonglong2 xq = xp[0];                   // x[0]
    xp += 2;                                 // -> x[1]

    // ---- Peel i=0: h0[0] = tanh(b0 + x0.Wih0) ----
    {
        ull a0 = ffma2(xq.x, wih0s[0], pb0);
        ull a1 = ffma2(xq.y, wih0s[1], 0ull);
        float s0 = hsum2(a0, a1);
        s0 += __shfl_xor_sync(FULLMASK, s0, 16);
        float h0n = fast_tanh_scaled(s0);
        if (ks == 0) sbuf[0][jidx] = h0n;
        __syncthreads();
        xq = xp[0]; xp += 2;                 // x[1]
    }

    float h1n = 0.f;

    // Body: compute h0[i] (from h0[i-1] in buf RH0, x[i]) and h1[i-1]
    // (from buf RH0 and h1[i-2] in buf RH1); store to WH0/WH1; one barrier.
    // Buffer indices are compile-time -> addresses are khoff/jidx + immediate.
#define STEP_BODY(RH0, RH1, WH0, WH1, PF)                                        \
    {                                                                            \
        const ulonglong2* hp0 = (const ulonglong2*)(&sbuf[RH0][khoff]);          \
        const ulonglong2* hp1 = (const ulonglong2*)(&sbuf[RH1][khoff]);          \
        ull a0 = ffma2(xq.x, wih0s[0], pb0);                                     \
        ull a1 = ffma2(xq.y, wih0s[1], 0ull);                                    \
        ull c0 = pb1, c1 = 0, c2 = 0, c3 = 0;                                    \
        ulonglong2 nxq;                                                          \
        if (PF) { nxq = xp[0]; xp += 2; }                                        \
        _Pragma("unroll")                                                        \
        for (int q = 0; q < 8; q++) {                                            \
            ulonglong2 hv = hp0[q];                                              \
            a0 = ffma2(hv.x, whh0h[2*q],   a0);                                  \
            a1 = ffma2(hv.y, whh0h[2*q+1], a1);                                  \
            c0 = ffma2(hv.x, wih1h[2*q],   c0);                                  \
            c1 = ffma2(hv.y, wih1h[2*q+1], c1);                                  \
        }                                                                        \
        _Pragma("unroll")                                                        \
        for (int q = 0; q < 8; q++) {                                            \
            ulonglong2 hv = hp1[q];                                              \
            c2 = ffma2(hv.x, whh1h[2*q],   c2);                                  \
            c3 = ffma2(hv.y, whh1h[2*q+1], c3);                                  \
        }                                                                        \
        float s0 = hsum2(a0, a1);                                                \
        s0 += __shfl_xor_sync(FULLMASK, s0, 16);                                 \
        float h0n = fast_tanh_scaled(s0);                                        \
        float s1 = hsum4(c0, c1, c2, c3);                                        \
        s1 += __shfl_xor_sync(FULLMASK, s1, 16);                                 \
        h1n = fast_tanh_scaled(s1);                                              \
        if (ks == 0) sbuf[WH0][jidx] = h0n;                                      \
        else         sbuf[WH1][jidx] = h1n;                                      \
        __syncthreads();                                                         \
        if (PF) xq = nxq;                                                        \
    }

    // i = 1..510 as 255 unrolled pairs (odd parity then even parity).
    for (int iu = 0; iu < 255; iu++) {
        STEP_BODY(0, 3, 1, 2, 1);   // i odd:  h0r=buf0, h1r=buf3 -> buf1, buf2
        STEP_BODY(1, 2, 0, 3, 1);   // i even: h0r=buf1, h1r=buf2 -> buf0, buf3
    }
    STEP_BODY(0, 3, 1, 2, 0);       // i = 511
#undef STEP_BODY

    // ---- Tail: h1[511] from h0[511] (buf1) and h1[510] (buf2) ----
    {
        const ulonglong2* hp0 = (const ulonglong2*)(&sbuf[1][khoff]);
        const ulonglong2* hp1 = (const ulonglong2*)(&sbuf[2][khoff]);
        ull c0 = pb1, c1 = 0, c2 = 0, c3 = 0;
        #pragma unroll
        for (int q = 0; q < 8; q++) {
            ulonglong2 hv = hp0[q];
            c0 = ffma2(hv.x, wih1h[2*q],   c0);
            c1 = ffma2(hv.y, wih1h[2*q+1], c1);
        }
        #pragma unroll
        for (int q = 0; q < 8; q++) {
            ulonglong2 hv = hp1[q];
            c2 = ffma2(hv.x, whh1h[2*q],   c2);
            c3 = ffma2(hv.y, whh1h[2*q+1], c3);
        }
        float s1 = hsum4(c0, c1, c2, c3);
        s1 += __shfl_xor_sync(FULLMASK, s1, 16);
        h1n = fast_tanh_scaled(s1);
    }

    // ---- FC: out[e] = sum_j h1_last[j] * fc_w[j] + fc_b ----
    float v = h1n * fcw;                     // fcw==0 on ks=1 lanes
    #pragma unroll
    for (int off = 16; off > 0; off >>= 1)
        v += __shfl_xor_sync(FULLMASK, v, off);
    if (lane == 0) sfc[warp] = v;
    __syncthreads();
    if (tid == 0)
        out[e] = sfc[0] + sfc[1] + sfc[2] + sfc[3] + fc_b[0];
}

extern "C" void kernel_launch(void* const* d_in, const int* in_sizes, int n_in,
                              void* d_out, int out_size)
{
    const float* x     = (const float*)d_in[0];
    const float* W_ih0 = (const float*)d_in[1];
    const float* W_hh0 = (const float*)d_in[2];
    const float* b_ih0 = (const float*)d_in[3];
    const float* b_hh0 = (const float*)d_in[4];
    const float* W_ih1 = (const float*)d_in[5];
    const float* W_hh1 = (const float*)d_in[6];
    const float* b_ih1 = (const float*)d_in[7];
    const float* b_hh1 = (const float*)d_in[8];
    const float* fc_w  = (const float*)d_in[9];
    const float* fc_b  = (const float*)d_in[10];
    float* out = (float*)d_out;

    dim3 grid(BB);          // 2048 blocks, one batch element each
    dim3 block(NTHREADS);   // 128 threads = 4 warps
    rnn_diet4_kernel<<<grid, block>>>(
        x, W_ih0, W_hh0, b_ih0, b_hh0,
        W_ih1, W_hh1, b_ih1, b_hh1,
        fc_w, fc_b, out);
}

// round 14
// speedup vs baseline: 1.0002x; 1.0002x over previous
#include <cuda_runtime.h>

// RNNModel: 2-layer tanh RNN + FC, B=2048, T=512, I=8, H=64.
// R12: R11 diet kernel squeezed to 128 regs for 4 blocks/SM (16 warps).
//  - __launch_bounds__(128, 4): reg cap 128 (R9 proved 96 weight regs fit).
//  - All four h buffers in ONE contiguous shared array -> every LDS/STS is
//    one khoff/jidx register + compile-time immediate (fewer address regs).
//  - Otherwise identical to R11: weights pre-scaled by 2*log2(e), bias folded
//    into ks==0 accumulator init, x-term split across k-halves, lag-1 layer
//    pipeline, 1 bar/step, parity unroll x2, skewed broadcast LDS.

#define TT 512
#define HH 64
#define NTHREADS 128
#define BB 2048
#define FULLMASK 0xffffffffu
#define HROW 72          // 64 + skew pad; half0 at [0,32), half1 at [36,68)
#define LOG2E2 2.8853900817779268f   // 2*log2(e)

typedef unsigned long long ull;

__device__ __forceinline__ ull ffma2(ull a, ull b, ull c) {
    ull d; asm("fma.rn.f32x2 %0, %1, %2, %3;" : "=l"(d) : "l"(a), "l"(b), "l"(c)); return d;
}
__device__ __forceinline__ ull fadd2(ull a, ull b) {
    ull d; asm("add.rn.f32x2 %0, %1, %2;" : "=l"(d) : "l"(a), "l"(b)); return d;
}
__device__ __forceinline__ ull fmul2(ull a, ull b) {
    ull d; asm("mul.rn.f32x2 %0, %1, %2;" : "=l"(d) : "l"(a), "l"(b)); return d;
}
__device__ __forceinline__ ull pack2(float lo, float hi) {
    ull d; asm("mov.b64 %0, {%1, %2};" : "=l"(d) : "f"(lo), "f"(hi)); return d;
}
__device__ __forceinline__ float hsum1(ull a) {
    float2 f; asm("mov.b64 {%0, %1}, %2;" : "=f"(f.x), "=f"(f.y) : "l"(a));
    return f.x + f.y;
}
__device__ __forceinline__ float hsum2(ull a, ull b) { return hsum1(fadd2(a, b)); }
__device__ __forceinline__ float hsum4(ull a0, ull a1, ull a2, ull a3) {
    return hsum1(fadd2(fadd2(a0, a1), fadd2(a2, a3)));
}
// Argument is PRE-SCALED by 2*log2(e): tanh(z) = 1 - 2/(exp2(z*2log2e)+1).
__device__ __forceinline__ float fast_tanh_scaled(float zs) {
    float e; asm("ex2.approx.f32 %0, %1;" : "=f"(e) : "f"(zs));
    float r; asm("rcp.approx.f32 %0, %1;" : "=f"(r) : "f"(e + 1.f));
    return fmaf(-2.f, r, 1.f);
}

__global__ void __launch_bounds__(NTHREADS, 4)
rnn_diet4_kernel(const float* __restrict__ x,
                 const float* __restrict__ W_ih0,
                 const float* __restrict__ W_hh0,
                 const float* __restrict__ b_ih0,
                 const float* __restrict__ b_hh0,
                 const float* __restrict__ W_ih1,
                 const float* __restrict__ W_hh1,
                 const float* __restrict__ b_ih1,
                 const float* __restrict__ b_hh1,
                 const float* __restrict__ fc_w,
                 const float* __restrict__ fc_b,
                 float* __restrict__ out)
{
    // One contiguous block: [0]=h0 parity0, [1]=h0 parity1,
    //                       [2]=h1 parity0, [3]=h1 parity1.
    __shared__ __align__(16) float sbuf[4][HROW];
    __shared__ float sfc[4];

    const int tid  = threadIdx.x;
    const int warp = tid >> 5;
    const int lane = tid & 31;
    const int jl   = lane & 15;
    const int ks   = lane >> 4;              // k half
    const int j    = warp * 16 + jl;
    const int jidx = j + ((j >> 5) << 2);    // skewed store index
    const int khoff = ks * 36;               // skewed read offset (floats)
    const int e    = blockIdx.x;

    if (tid < HROW) { sbuf[2][tid] = 0.f; sbuf[3][tid] = 0.f; }

    const ull CC = pack2(LOG2E2, LOG2E2);

    // ---- Per-lane half-k weight rows, PRE-SCALED by 2log2e ----
    ull whh0h[16], wih1h[16], whh1h[16], wih0s[2];
    {
        const ulonglong2* p = (const ulonglong2*)(W_hh0 + j * HH + ks * 32);
        #pragma unroll
        for (int i = 0; i < 8; i++) {
            ulonglong2 v = p[i];
            whh0h[2*i] = fmul2(v.x, CC); whh0h[2*i+1] = fmul2(v.y, CC);
        }
    }
    {
        const ulonglong2* p = (const ulonglong2*)(W_ih1 + j * HH + ks * 32);
        #pragma unroll
        for (int i = 0; i < 8; i++) {
            ulonglong2 v = p[i];
            wih1h[2*i] = fmul2(v.x, CC); wih1h[2*i+1] = fmul2(v.y, CC);
        }
    }
    {
        const ulonglong2* p = (const ulonglong2*)(W_hh1 + j * HH + ks * 32);
        #pragma unroll
        for (int i = 0; i < 8; i++) {
            ulonglong2 v = p[i];
            whh1h[2*i] = fmul2(v.x, CC); whh1h[2*i+1] = fmul2(v.y, CC);
        }
    }
    {   // W_ih0 row j, this lane's k-quarter of I=8: cols [ks*4, ks*4+4)
        const ulonglong2* p = (const ulonglong2*)(W_ih0 + j * 8 + ks * 4);
        ulonglong2 v = p[0];
        wih0s[0] = fmul2(v.x, CC); wih0s[1] = fmul2(v.y, CC);
    }

    // Biases pre-scaled, packed as (b, 0) -- ONLY on the ks==0 half so the
    // cross-half shfl reduce counts each bias exactly once.
    ull pb0 = pack2((b_ih0[j] + b_hh0[j]) * LOG2E2, 0.f);
    ull pb1 = pack2((b_ih1[j] + b_hh1[j]) * LOG2E2, 0.f);
    if (ks == 1) { pb0 = 0ull; pb1 = 0ull; }

    float fcw = fc_w[j];
    if (ks == 1) fcw = 0.f;                  // count each j once in FC reduce

    __syncthreads();

    // x: lane reads its k-quarter (float4) of step t: index t*2 + ks (ulonglong2).
    const ulonglong2* xp = (const ulonglong2*)(x + (size_t)e * TT * 8) + ks;
    ulonglong2 xq = xp[0];                   // x[0]
    xp += 2;                                 // -> x[1]

    // ---- Peel i=0: h0[0] = tanh(b0 + x0.Wih0) ----
    {
        ull a0 = ffma2(xq.x, wih0s[0], pb0);
        ull a1 = ffma2(xq.y, wih0s[1], 0ull);
        float s0 = hsum2(a0, a1);
        s0 += __shfl_xor_sync(FULLMASK, s0, 16);
        float h0n = fast_tanh_scaled(s0);
        if (ks == 0) sbuf[0][jidx] = h0n;
        __syncthreads();
        xq = xp[0]; xp += 2;                 // x[1]
    }

    float h1n = 0.f;

    // Body: compute h0[i] (from h0[i-1] in buf RH0, x[i]) and h1[i-1]
    // (from buf RH0 and h1[i-2] in buf RH1); store to WH0/WH1; one barrier.
    // Buffer indices are compile-time -> addresses are khoff/jidx + immediate.
#define STEP_BODY(RH0, RH1, WH0, WH1, PF)                                        \
    {                                                                            \
        const ulonglong2* hp0 = (const ulonglong2*)(&sbuf[RH0][khoff]);          \
        const ulonglong2* hp1 = (const ulonglong2*)(&sbuf[RH1][khoff]);          \
        ull a0 = ffma2(xq.x, wih0s[0], pb0);                                     \
        ull a1 = ffma2(xq.y, wih0s[1], 0ull);                                    \
        ull c0 = pb1, c1 = 0, c2 = 0, c3 = 0;                                    \
        ulonglong2 nxq;                                                          \
        if (PF) { nxq = xp[0]; xp += 2; }                                        \
        _Pragma("unroll")                                                        \
        for (int q = 0; q < 8; q++) {                                            \
            ulonglong2 hv = hp0[q];                                              \
            a0 = ffma2(hv.x, whh0h[2*q],   a0);                                  \
            a1 = ffma2(hv.y, whh0h[2*q+1], a1);                                  \
            c0 = ffma2(hv.x, wih1h[2*q],   c0);                                  \
            c1 = ffma2(hv.y, wih1h[2*q+1], c1);                                  \
        }                                                                        \
        _Pragma("unroll")                                                        \
        for (int q = 0; q < 8; q++) {                                            \
            ulonglong2 hv = hp1[q];                                              \
            c2 = ffma2(hv.x, whh1h[2*q],   c2);                                  \
            c3 = ffma2(hv.y, whh1h[2*q+1], c3);                                  \
        }                                                                        \
        float s0 = hsum2(a0, a1);                                                \
        s0 += __shfl_xor_sync(FULLMASK, s0, 16);                                 \
        float h0n = fast_tanh_scaled(s0);                                        \
        float s1 = hsum4(c0, c1, c2, c3);                                        \
        s1 += __shfl_xor_sync(FULLMASK, s1, 16);                                 \
        h1n = fast_tanh_scaled(s1);                                              \
        if (ks == 0) sbuf[WH0][jidx] = h0n;                                      \
        else         sbuf[WH1][jidx] = h1n;                                      \
        __syncthreads();                                                         \
        if (PF) xq = nxq;                                                        \
    }

    // i = 1..510 as 255 unrolled pairs (odd parity then even parity).
    for (int iu = 0; iu < 255; iu++) {
        STEP_BODY(0, 3, 1, 2, 1);   // i odd:  h0r=buf0, h1r=buf3 -> buf1, buf2
        STEP_BODY(1, 2, 0, 3, 1);   // i even: h0r=buf1, h1r=buf2 -> buf0, buf3
    }
    STEP_BODY(0, 3, 1, 2, 0);       // i = 511
#undef STEP_BODY

    // ---- Tail: h1[511] from h0[511] (buf1) and h1[510] (buf2) ----
    {
        const ulonglong2* hp0 = (const ulonglong2*)(&sbuf[1][khoff]);
        const ulonglong2* hp1 = (const ulonglong2*)(&sbuf[2][khoff]);
        ull c0 = pb1, c1 = 0, c2 = 0, c3 = 0;
        #pragma unroll
        for (int q = 0; q < 8; q++) {
            ulonglong2 hv = hp0[q];
            c0 = ffma2(hv.x, wih1h[2*q],   c0);
            c1 = ffma2(hv.y, wih1h[2*q+1], c1);
        }
        #pragma unroll
        for (int q = 0; q < 8; q++) {
            ulonglong2 hv = hp1[q];
            c2 = ffma2(hv.x, whh1h[2*q],   c2);
            c3 = ffma2(hv.y, whh1h[2*q+1], c3);
        }
        float s1 = hsum4(c0, c1, c2, c3);
        s1 += __shfl_xor_sync(FULLMASK, s1, 16);
        h1n = fast_tanh_scaled(s1);
    }

    // ---- FC: out[e] = sum_j h1_last[j] * fc_w[j] + fc_b ----
    float v = h1n * fcw;                     // fcw==0 on ks=1 lanes
    #pragma unroll
    for (int off = 16; off > 0; off >>= 1)
        v += __shfl_xor_sync(FULLMASK, v, off);
    if (lane == 0) sfc[warp] = v;
    __syncthreads();
    if (tid == 0)
        out[e] = sfc[0] + sfc[1] + sfc[2] + sfc[3] + fc_b[0];
}

extern "C" void kernel_launch(void* const* d_in, const int* in_sizes, int n_in,
                              void* d_out, int out_size)
{
    const float* x     = (const float*)d_in[0];
    const float* W_ih0 = (const float*)d_in[1];
    const float* W_hh0 = (const float*)d_in[2];
    const float* b_ih0 = (const float*)d_in[3];
    const float* b_hh0 = (const float*)d_in[4];
    const float* W_ih1 = (const float*)d_in[5];
    const float* W_hh1 = (const float*)d_in[6];
    const float* b_ih1 = (const float*)d_in[7];
    const float* b_hh1 = (const float*)d_in[8];
    const float* fc_w  = (const float*)d_in[9];
    const float* fc_b  = (const float*)d_in[10];
    float* out = (float*)d_out;

    dim3 grid(BB);          // 2048 blocks, one batch element each
    dim3 block(NTHREADS);   // 128 threads = 4 warps
    rnn_diet4_kernel<<<grid, block>>>(
        x, W_ih0, W_hh0, b_ih0, b_hh0,
        W_ih1, W_hh1, b_ih1, b_hh1,
        fc_w, fc_b, out);
}